// round 4
// baseline (speedup 1.0000x reference)
#include <cuda_runtime.h>
#include <math.h>

#define B_   4
#define N_   8192
#define F_   64
#define NIN_ 67

#define S_OFF 0
#define F_OFF (B_ * N_)
#define C_OFF (B_ * N_ + B_ * N_ * F_)

// ---------------- scratch (no allocations allowed) ----------------
__device__ int   g_mask_mode;              // 0=byte, 1=int32, 2=float32
__device__ float g_comp[B_][N_][3];        // compacted selected points per batch

// ---------------- f32x2 helpers (sm_103a packed fp32) ----------------
static __device__ __forceinline__ unsigned long long pack2(float lo, float hi) {
    unsigned long long r;
    asm("mov.b64 %0, {%1, %2};" : "=l"(r) : "f"(lo), "f"(hi));
    return r;
}
static __device__ __forceinline__ void unpack2(unsigned long long v, float& lo, float& hi) {
    asm("mov.b64 {%0, %1}, %2;" : "=f"(lo), "=f"(hi) : "l"(v));
}
static __device__ __forceinline__ unsigned long long ffma2(
    unsigned long long a, unsigned long long b, unsigned long long c) {
    unsigned long long d;
    asm("fma.rn.f32x2 %0, %1, %2, %3;" : "=l"(d) : "l"(a), "l"(b), "l"(c));
    return d;
}

static __device__ __forceinline__ bool read_mask(const void* m, int idx, int mode) {
    if (mode == 1) return ((const int*)m)[idx] != 0;
    if (mode == 2) return ((const float*)m)[idx] != 0.0f;
    return ((const unsigned char*)m)[idx] != 0;
}

// ---------------- kernel 0: detect leaf_mask storage dtype ----------------
// Reads the first 8192 32-bit words (= 32768 bytes, in-bounds for byte/int/float
// storage of 32768 elements). Random 0/1 data makes the classification unambiguous.
__global__ void detect_mask_kernel(const unsigned int* __restrict__ mw) {
    __shared__ int fl[2];
    if (threadIdx.x < 2) fl[threadIdx.x] = 0;
    __syncthreads();
    int bad01 = 0, badf = 0;
    for (int i = threadIdx.x; i < N_; i += blockDim.x) {
        unsigned int v = mw[i];
        if (v > 1u) bad01 = 1;
        if (v != 0u && v != 0x3F800000u) badf = 1;
    }
    if (bad01) atomicOr(&fl[0], 1);
    if (badf)  atomicOr(&fl[1], 1);
    __syncthreads();
    if (threadIdx.x == 0)
        g_mask_mode = (!fl[0]) ? 1 : ((!fl[1]) ? 2 : 0);
}

// ---------------- kernel 1: MLP scores + feature passthrough ----------------
// One thread per point. Weights pre-packed into shared as f32x2 neuron pairs.
__global__ void __launch_bounds__(256)
mlp_kernel(const float* __restrict__ points, const float* __restrict__ features,
           const void* __restrict__ mask,
           const float* __restrict__ W1, const float* __restrict__ b1,
           const float* __restrict__ W2, const float* __restrict__ b2,
           const float* __restrict__ W3, const float* __restrict__ b3,
           float* __restrict__ out) {
    __shared__ unsigned long long sW1[NIN_ * 32];  // [j][p] = (W1[2p][j], W1[2p+1][j])
    __shared__ unsigned long long sB1[32];
    __shared__ unsigned long long sW2[64 * 16];    // [j][q] = (W2[2q][j], W2[2q+1][j])
    __shared__ unsigned long long sB2[16];
    __shared__ float sW3[32];
    __shared__ float sB3v;

    const int tid = threadIdx.x;
    for (int idx = tid; idx < NIN_ * 32; idx += 256) {
        int j = idx >> 5, p = idx & 31;
        sW1[idx] = pack2(W1[(2 * p) * NIN_ + j], W1[(2 * p + 1) * NIN_ + j]);
    }
    for (int idx = tid; idx < 64 * 16; idx += 256) {
        int j = idx >> 4, q = idx & 15;
        sW2[idx] = pack2(W2[(2 * q) * 64 + j], W2[(2 * q + 1) * 64 + j]);
    }
    if (tid < 32) sB1[tid] = pack2(b1[2 * tid], b1[2 * tid + 1]);
    if (tid < 16) sB2[tid] = pack2(b2[2 * tid], b2[2 * tid + 1]);
    if (tid < 32) sW3[tid] = W3[tid];
    if (tid == 0) sB3v = b3[0];
    __syncthreads();

    const int gp = blockIdx.x * 256 + tid;  // global point id in [0, 32768)

    // Load features (needed for MLP anyway) and pass them through to the output.
    const float4* Fv = (const float4*)features + gp * 16;
    float4*       Ov = (float4*)(out + F_OFF) + gp * 16;
    float xr[NIN_];
#pragma unroll
    for (int k = 0; k < 16; k++) {
        float4 v = Fv[k];
        Ov[k] = v;
        xr[4 * k + 0] = v.x; xr[4 * k + 1] = v.y;
        xr[4 * k + 2] = v.z; xr[4 * k + 3] = v.w;
    }
    xr[64] = points[gp * 3 + 0];
    xr[65] = points[gp * 3 + 1];
    xr[66] = points[gp * 3 + 2];

    const bool m = read_mask(mask, gp, g_mask_mode);
    float score = 0.0f;
    if (__any_sync(0xFFFFFFFFu, m)) {
        // Layer 1: 64 neurons as 32 packed pairs
        unsigned long long acc[32];
#pragma unroll
        for (int p = 0; p < 32; p++) acc[p] = sB1[p];
#pragma unroll
        for (int j = 0; j < NIN_; j++) {
            unsigned long long xx = pack2(xr[j], xr[j]);
#pragma unroll
            for (int p = 0; p < 32; p++) acc[p] = ffma2(xx, sW1[j * 32 + p], acc[p]);
        }
        float h1[64];
#pragma unroll
        for (int p = 0; p < 32; p++) {
            float lo, hi;
            unpack2(acc[p], lo, hi);
            h1[2 * p]     = fmaxf(lo, 0.0f);
            h1[2 * p + 1] = fmaxf(hi, 0.0f);
        }
        // Layer 2: 32 neurons as 16 packed pairs
        unsigned long long acc2[16];
#pragma unroll
        for (int q = 0; q < 16; q++) acc2[q] = sB2[q];
#pragma unroll
        for (int j = 0; j < 64; j++) {
            unsigned long long hh = pack2(h1[j], h1[j]);
#pragma unroll
            for (int q = 0; q < 16; q++) acc2[q] = ffma2(hh, sW2[j * 16 + q], acc2[q]);
        }
        // Layer 3 + sigmoid
        float z = sB3v;
#pragma unroll
        for (int q = 0; q < 16; q++) {
            float lo, hi;
            unpack2(acc2[q], lo, hi);
            z += fmaxf(lo, 0.0f) * sW3[2 * q] + fmaxf(hi, 0.0f) * sW3[2 * q + 1];
        }
        score = 1.0f / (1.0f + expf(-z));
    }
    out[S_OFF + gp] = m ? score : 0.0f;  // scores = mlp(x) * mask
}

// ---------------- kernel 2: per-batch reductions / confidence ----------------
// One 1024-thread block per batch; 8 contiguous points per thread.
__global__ void __launch_bounds__(1024)
finalize_kernel(const float* __restrict__ points, const void* __restrict__ mask,
                float* __restrict__ out) {
    const int b   = blockIdx.x;
    const int tid = threadIdx.x;
    float*       scores = out + S_OFF + b * N_;
    const float* pts    = points + (size_t)b * N_ * 3;
    const int    mbase  = b * N_;
    const int    mode   = g_mask_mode;

    __shared__ double shd [1024];
    __shared__ double shd2[1024];
    __shared__ int    shi [1024];
    __shared__ int    wsum[32];

    // ---- phase 1: n_leaf = sum(mask) ----
    int lc = 0;
#pragma unroll
    for (int k = 0; k < 8; k++)
        lc += read_mask(mask, mbase + tid * 8 + k, mode) ? 1 : 0;
    shi[tid] = lc;
    __syncthreads();
    for (int s = 512; s > 0; s >>= 1) {
        if (tid < s) shi[tid] += shi[tid + s];
        __syncthreads();
    }
    const int n_leaf = shi[0];
    __syncthreads();

    // ---- phase 2: apply n_leaf<10 zeroing; accumulate sum(s), sum(s^2) ----
    const float zfac = (n_leaf < 10) ? 0.0f : 1.0f;
    double ls = 0.0, ls2 = 0.0;
    float  sv[8];
#pragma unroll
    for (int k = 0; k < 8; k++) {
        int   n = tid * 8 + k;
        float s = scores[n] * zfac;  // scores already include mask factor (0 off-mask)
        sv[k]     = s;
        scores[n] = s;               // final boundary_prob
        ls  += s;
        ls2 += (double)s * (double)s;
    }
    shd[tid] = ls; shd2[tid] = ls2;
    __syncthreads();
    for (int s = 512; s > 0; s >>= 1) {
        if (tid < s) { shd[tid] += shd[tid + s]; shd2[tid] += shd2[tid + s]; }
        __syncthreads();
    }
    const double Ss = shd[0], Ss2 = shd2[0];
    __syncthreads();

    // ---- phase 3: sel = s > 0.7; stable compaction by index (== argsort order) ----
    int c = 0;
#pragma unroll
    for (int k = 0; k < 8; k++) c += (sv[k] > 0.7f) ? 1 : 0;
    const int lane = tid & 31, wid = tid >> 5;
    int incl = c;
#pragma unroll
    for (int o = 1; o < 32; o <<= 1) {
        int t = __shfl_up_sync(0xFFFFFFFFu, incl, o);
        if (lane >= o) incl += t;
    }
    if (lane == 31) wsum[wid] = incl;
    __syncthreads();
    if (wid == 0) {
        int v = wsum[lane];
#pragma unroll
        for (int o = 1; o < 32; o <<= 1) {
            int t = __shfl_up_sync(0xFFFFFFFFu, v, o);
            if (lane >= o) v += t;
        }
        wsum[lane] = v;
    }
    __syncthreads();
    int       pos = incl - c + ((wid > 0) ? wsum[wid - 1] : 0);
    const int cnt = wsum[31];
#pragma unroll
    for (int k = 0; k < 8; k++) {
        if (sv[k] > 0.7f) {
            int n = tid * 8 + k;
            g_comp[b][pos][0] = pts[n * 3 + 0];
            g_comp[b][pos][1] = pts[n * 3 + 1];
            g_comp[b][pos][2] = pts[n * 3 + 2];
            pos++;
        }
    }
    __syncthreads();  // block-wide visibility of g_comp writes

    // ---- phase 4: consecutive distances among selected points ----
    double ld = 0.0, ld2 = 0.0;
    for (int k = tid; k < cnt - 1; k += 1024) {
        float dx = g_comp[b][k + 1][0] - g_comp[b][k][0];
        float dy = g_comp[b][k + 1][1] - g_comp[b][k][1];
        float dz = g_comp[b][k + 1][2] - g_comp[b][k][2];
        float dd = sqrtf(dx * dx + dy * dy + dz * dz);
        ld  += dd;
        ld2 += (double)dd * (double)dd;
    }
    shd[tid] = ld; shd2[tid] = ld2;
    __syncthreads();
    for (int s = 512; s > 0; s >>= 1) {
        if (tid < s) { shd[tid] += shd[tid + s]; shd2[tid] += shd2[tid + s]; }
        __syncthreads();
    }

    if (tid == 0) {
        const double Sd = shd[0], Sd2 = shd2[0];
        // clarity = unbiased masked var of scores
        double nl    = (double)n_leaf;
        double meanS = Ss / fmax(nl, 1.0);
        float  clarity = (float)((Ss2 - nl * meanS * meanS) / fmax(nl - 1.0, 1.0));
        // dvar = unbiased masked var of the cnt-1 consecutive distances
        int np = cnt - 1; if (np < 0) np = 0;
        double dnp   = (double)np;
        double meanD = Sd / fmax(dnp, 1.0);
        float  dvar  = (float)((Sd2 - dnp * meanD * meanD) / fmax(dnp - 1.0, 1.0));
        float cont = 1.0f / (dvar + 1e-8f);
        cont = fminf(fmaxf(cont, 0.0f), 1.0f);
        if (!(cnt > 5)) cont = 0.0f;
        float conf = fminf(fmaxf(clarity * cont, 0.0f), 1.0f);
        if (n_leaf == 0) conf = 0.0f;
        out[C_OFF + b] = conf;
    }
}

// ---------------- launch ----------------
extern "C" void kernel_launch(void* const* d_in, const int* in_sizes, int n_in,
                              void* d_out, int out_size) {
    const float* points   = (const float*)d_in[0];
    const float* features = (const float*)d_in[1];
    const void*  mask     = d_in[2];
    const float* W1 = (const float*)d_in[3];
    const float* b1 = (const float*)d_in[4];
    const float* W2 = (const float*)d_in[5];
    const float* b2 = (const float*)d_in[6];
    const float* W3 = (const float*)d_in[7];
    const float* b3 = (const float*)d_in[8];
    float* out = (float*)d_out;

    detect_mask_kernel<<<1, 256>>>((const unsigned int*)mask);
    mlp_kernel<<<(B_ * N_) / 256, 256>>>(points, features, mask,
                                         W1, b1, W2, b2, W3, b3, out);
    finalize_kernel<<<B_, 1024>>>(points, mask, out);
}